// round 9
// baseline (speedup 1.0000x reference)
#include <cuda_runtime.h>
#include <cstring>

// Fused JPEG round-trip. Thread owns row r of ONE 8x8 block: Y scalar (8 regs),
// U+V packed f32x2 (16 regs). Transposes via per-warp conflict-free smem with
// eager per-channel spill-to-smem to cap register peak at 48 -> 5 CTAs/SM.
// Input : d_in[0] = float32 [1,3,2048,2048]; Output: float32 [1,3*2048*2048]

#define IMG_W  2048
#define IMG_H  2048
#define PLANE  (IMG_W * IMG_H)

#define C1 0.4903926402f
#define C2 0.4619397663f
#define C3 0.4157348062f
#define C4 0.3535533906f
#define C5 0.2777851165f
#define C6 0.1913417162f
#define C7 0.0975451610f

__constant__ float cQf[128] = {
    16,11,10,16,24,40,51,61,  12,12,14,19,26,58,60,55,
    14,13,16,24,40,57,69,56,  14,17,22,29,51,87,80,62,
    18,22,37,56,68,109,103,77, 24,35,55,64,81,104,113,92,
    49,64,78,87,103,121,120,101, 72,92,95,98,112,100,103,99,
    17,18,24,47,99,99,99,99,  18,21,26,66,99,99,99,99,
    24,26,56,99,99,99,99,99,  47,66,99,99,99,99,99,99,
    99,99,99,99,99,99,99,99,  99,99,99,99,99,99,99,99,
    99,99,99,99,99,99,99,99,  99,99,99,99,99,99,99,99 };
__constant__ float cRQf[128] = {
    1.f/16,1.f/11,1.f/10,1.f/16,1.f/24,1.f/40,1.f/51,1.f/61,
    1.f/12,1.f/12,1.f/14,1.f/19,1.f/26,1.f/58,1.f/60,1.f/55,
    1.f/14,1.f/13,1.f/16,1.f/24,1.f/40,1.f/57,1.f/69,1.f/56,
    1.f/14,1.f/17,1.f/22,1.f/29,1.f/51,1.f/87,1.f/80,1.f/62,
    1.f/18,1.f/22,1.f/37,1.f/56,1.f/68,1.f/109,1.f/103,1.f/77,
    1.f/24,1.f/35,1.f/55,1.f/64,1.f/81,1.f/104,1.f/113,1.f/92,
    1.f/49,1.f/64,1.f/78,1.f/87,1.f/103,1.f/121,1.f/120,1.f/101,
    1.f/72,1.f/92,1.f/95,1.f/98,1.f/112,1.f/100,1.f/103,1.f/99,
    1.f/17,1.f/18,1.f/24,1.f/47,1.f/99,1.f/99,1.f/99,1.f/99,
    1.f/18,1.f/21,1.f/26,1.f/66,1.f/99,1.f/99,1.f/99,1.f/99,
    1.f/24,1.f/26,1.f/56,1.f/99,1.f/99,1.f/99,1.f/99,1.f/99,
    1.f/47,1.f/66,1.f/99,1.f/99,1.f/99,1.f/99,1.f/99,1.f/99,
    1.f/99,1.f/99,1.f/99,1.f/99,1.f/99,1.f/99,1.f/99,1.f/99,
    1.f/99,1.f/99,1.f/99,1.f/99,1.f/99,1.f/99,1.f/99,1.f/99,
    1.f/99,1.f/99,1.f/99,1.f/99,1.f/99,1.f/99,1.f/99,1.f/99,
    1.f/99,1.f/99,1.f/99,1.f/99,1.f/99,1.f/99,1.f/99,1.f/99 };

// Folded inverse-color + normalization on raw (y,u,v):
// out_c = NC_Ac*y + NC_Bc*u + NC_Cc*v + NC_Kc   (validated R5-R7)
#define NC_A0 0.0158730159f
#define NC_B0 (-1.93476190e-8f)
#define NC_C0 0.0222539619f
#define NC_K0 (-4.8373935f)
#define NC_A1 0.0161030596f
#define NC_B1 (-0.0055416377f)
#define NC_C1 (-0.0114997768f)
#define NC_K1 0.2006247f
#define NC_A2 0.0149925037f
#define NC_B2 0.0265667181f
#define NC_C2 6.09145427e-9f
#define NC_K2 (-5.1081869f)

typedef unsigned long long ull;

// ---- packed f32x2 helpers ----
__device__ __forceinline__ ull pk(float lo, float hi) {
    float2 t = make_float2(lo, hi); ull r; memcpy(&r, &t, 8); return r;
}
__device__ __forceinline__ ull pk1(float x) { return pk(x, x); }
__device__ __forceinline__ float2 unpk(ull a) {
    float2 t; memcpy(&t, &a, 8); return t;
}
__device__ __forceinline__ ull padd(ull a, ull b) {
    ull r; asm("add.rn.f32x2 %0,%1,%2;" : "=l"(r) : "l"(a), "l"(b)); return r;
}
__device__ __forceinline__ ull pmul(ull a, ull b) {
    ull r; asm("mul.rn.f32x2 %0,%1,%2;" : "=l"(r) : "l"(a), "l"(b)); return r;
}
__device__ __forceinline__ ull pfma(ull a, ull b, ull c) {
    ull r; asm("fma.rn.f32x2 %0,%1,%2,%3;" : "=l"(r) : "l"(a), "l"(b), "l"(c)); return r;
}
__device__ __forceinline__ ull psub(ull a, ull b) { return pfma(b, pk1(-1.0f), a); }

// ---- scalar 8-pt transforms ----
__device__ __forceinline__ void fdct8(float v[8]) {
    float e0=v[0]+v[7], e1=v[1]+v[6], e2=v[2]+v[5], e3=v[3]+v[4];
    float o0=v[0]-v[7], o1=v[1]-v[6], o2=v[2]-v[5], o3=v[3]-v[4];
    float s03=e0+e3, s12=e1+e2, d03=e0-e3, d12=e1-e2;
    v[0]=C4*(s03+s12);
    v[4]=C4*(s03-s12);
    v[2]=fmaf(C2,d03, C6*d12);
    v[6]=fmaf(C6,d03,-C2*d12);
    v[1]=fmaf(C1,o0,fmaf( C3,o1,fmaf( C5,o2, C7*o3)));
    v[3]=fmaf(C3,o0,fmaf(-C7,o1,fmaf(-C1,o2,-C5*o3)));
    v[5]=fmaf(C5,o0,fmaf(-C1,o1,fmaf( C7,o2, C3*o3)));
    v[7]=fmaf(C7,o0,fmaf(-C5,o1,fmaf( C3,o2,-C1*o3)));
}
__device__ __forceinline__ void idct8(float v[8]) {
    float sp=C4*(v[0]+v[4]), sm=C4*(v[0]-v[4]);
    float t1=fmaf(C2,v[2], C6*v[6]);
    float t2=fmaf(C6,v[2],-C2*v[6]);
    float E0=sp+t1, E1=sm+t2, E2=sm-t2, E3=sp-t1;
    float O0=fmaf(C1,v[1],fmaf( C3,v[3],fmaf( C5,v[5], C7*v[7])));
    float O1=fmaf(C3,v[1],fmaf(-C7,v[3],fmaf(-C1,v[5],-C5*v[7])));
    float O2=fmaf(C5,v[1],fmaf(-C1,v[3],fmaf( C7,v[5], C3*v[7])));
    float O3=fmaf(C7,v[1],fmaf(-C5,v[3],fmaf( C3,v[5],-C1*v[7])));
    v[0]=E0+O0; v[7]=E0-O0;
    v[1]=E1+O1; v[6]=E1-O1;
    v[2]=E2+O2; v[5]=E2-O2;
    v[3]=E3+O3; v[4]=E3-O3;
}

// ---- packed 8-pt transforms ----
__device__ __forceinline__ void fdct8p(ull v[8]) {
    ull e0=padd(v[0],v[7]), e1=padd(v[1],v[6]), e2=padd(v[2],v[5]), e3=padd(v[3],v[4]);
    ull o0=psub(v[0],v[7]), o1=psub(v[1],v[6]), o2=psub(v[2],v[5]), o3=psub(v[3],v[4]);
    ull s03=padd(e0,e3), s12=padd(e1,e2), d03=psub(e0,e3), d12=psub(e1,e2);
    v[0]=pmul(pk1(C4), padd(s03,s12));
    v[4]=pmul(pk1(C4), psub(s03,s12));
    v[2]=pfma(pk1(C2),d03, pmul(pk1( C6),d12));
    v[6]=pfma(pk1(C6),d03, pmul(pk1(-C2),d12));
    v[1]=pfma(pk1(C1),o0, pfma(pk1( C3),o1, pfma(pk1( C5),o2, pmul(pk1( C7),o3))));
    v[3]=pfma(pk1(C3),o0, pfma(pk1(-C7),o1, pfma(pk1(-C1),o2, pmul(pk1(-C5),o3))));
    v[5]=pfma(pk1(C5),o0, pfma(pk1(-C1),o1, pfma(pk1( C7),o2, pmul(pk1( C3),o3))));
    v[7]=pfma(pk1(C7),o0, pfma(pk1(-C5),o1, pfma(pk1( C3),o2, pmul(pk1(-C1),o3))));
}
__device__ __forceinline__ void idct8p(ull v[8]) {
    ull sp=pmul(pk1(C4), padd(v[0],v[4]));
    ull sm=pmul(pk1(C4), psub(v[0],v[4]));
    ull t1=pfma(pk1(C2),v[2], pmul(pk1( C6),v[6]));
    ull t2=pfma(pk1(C6),v[2], pmul(pk1(-C2),v[6]));
    ull E0=padd(sp,t1), E1=padd(sm,t2), E2=psub(sm,t2), E3=psub(sp,t1);
    ull O0=pfma(pk1(C1),v[1], pfma(pk1( C3),v[3], pfma(pk1( C5),v[5], pmul(pk1( C7),v[7]))));
    ull O1=pfma(pk1(C3),v[1], pfma(pk1(-C7),v[3], pfma(pk1(-C1),v[5], pmul(pk1(-C5),v[7]))));
    ull O2=pfma(pk1(C5),v[1], pfma(pk1(-C1),v[3], pfma(pk1( C7),v[5], pmul(pk1( C3),v[7]))));
    ull O3=pfma(pk1(C7),v[1], pfma(pk1(-C5),v[3], pfma(pk1( C3),v[5], pmul(pk1(-C1),v[7]))));
    v[0]=padd(E0,O0); v[7]=psub(E0,O0);
    v[1]=padd(E1,O1); v[6]=psub(E1,O1);
    v[2]=padd(E2,O2); v[5]=psub(E2,O2);
    v[3]=padd(E3,O3); v[4]=psub(E3,O3);
}

// smem layouts (conflict-free, as R8):
#define RPY 12
#define GPY 104
#define RPU 10
#define GPU 84

__device__ __forceinline__ void writeY(const float vy[8], float* ybg, int r) {
    float* yw = ybg + RPY * r;
    *(float4*)(yw)     = make_float4(vy[0], vy[1], vy[2], vy[3]);
    *(float4*)(yw + 4) = make_float4(vy[4], vy[5], vy[6], vy[7]);
}
__device__ __forceinline__ void writeUV(const ull uv[8], ull* uvbg, int r) {
    ull* uw = uvbg + RPU * r;
    #pragma unroll
    for (int k = 0; k < 8; k += 2)
        *(ulonglong2*)(uw + k) = make_ulonglong2(uv[k], uv[k+1]);
}
__device__ __forceinline__ void readY(float vy[8], const float* ybg, int r) {
    #pragma unroll
    for (int k = 0; k < 8; ++k) vy[k] = ybg[RPY * k + r];
}
__device__ __forceinline__ void readUV(ull uv[8], const ull* uvbg, int r) {
    #pragma unroll
    for (int k = 0; k < 8; ++k) uv[k] = uvbg[RPU * k + r];
}

__global__ __launch_bounds__(256, 5)
void jpeg_roundtrip_kernel(const float* __restrict__ in, float* __restrict__ out)
{
    __shared__ __align__(16) float yb[8 * 4 * GPY];   // 13312 B
    __shared__ __align__(16) ull  uvb[8 * 4 * GPU];   // 21504 B
    __shared__ float qt[256];                         // interleaved (q, rq)

    const int tid  = threadIdx.x;
    const int warp = tid >> 5;
    const int lane = tid & 31;
    const int r    = lane >> 2;
    const int g    = lane & 3;

    {   // build interleaved quant table
        int w  = tid & 1, rr = (tid >> 1) & 7, ii = (tid >> 4) & 7, ch = tid >> 7;
        int si = ch * 64 + ii * 8 + rr;
        qt[tid] = w ? cRQf[si] : cQf[si];
    }

    float* ybg  = yb  + (warp * 4 + g) * GPY;
    ull*   uvbg = uvb + (warp * 4 + g) * GPU;

    const int x0   = blockIdx.x * 256 + (warp * 4 + g) * 8;
    const int y    = blockIdx.y * 8 + r;
    const int base = y * IMG_W + x0;

    float vY[8];
    ull   pUV[8];

    // ---- load RGB + forward color (scalar U,V then pack) ----
    {
        const float4 Ra = *(const float4*)(in + base);
        const float4 Rb = *(const float4*)(in + base + 4);
        const float4 Ga = *(const float4*)(in + base + PLANE);
        const float4 Gb = *(const float4*)(in + base + PLANE + 4);
        const float4 Ba = *(const float4*)(in + base + 2*PLANE);
        const float4 Bb = *(const float4*)(in + base + 2*PLANE + 4);

        __syncthreads();   // quant table ready

        float R[8] = {Ra.x,Ra.y,Ra.z,Ra.w, Rb.x,Rb.y,Rb.z,Rb.w};
        float G[8] = {Ga.x,Ga.y,Ga.z,Ga.w, Gb.x,Gb.y,Gb.z,Gb.w};
        float B[8] = {Ba.x,Ba.y,Ba.z,Ba.w, Bb.x,Bb.y,Bb.z,Bb.w};
        #pragma unroll
        for (int k = 0; k < 8; ++k) {
            vY[k] = 0.299f*R[k] + 0.587f*G[k] + 0.114f*B[k];
            float u = fmaf(-0.168736f, R[k], fmaf(-0.331264f, G[k], fmaf(0.5f, B[k], 128.0f)));
            float v = fmaf(0.5f, R[k], fmaf(-0.418688f, G[k], fmaf(-0.081312f, B[k], 128.0f)));
            pUV[k] = pk(u, v);
        }
    }

    // ---- stage 1: row DCT, eager spill to smem per channel ----
    fdct8(vY);   writeY(vY, ybg, r);       // vY regs free during UV transform
    fdct8p(pUV); writeUV(pUV, uvbg, r);
    __syncwarp();
    readY(vY, ybg, r);
    readUV(pUV, uvbg, r);

    // ---- stage 2: column DCT + quant/dequant, channel-serialized ----
    fdct8(vY);
    #pragma unroll
    for (int i = 0; i < 8; ++i) {
        float2 qy = *(const float2*)(qt + i * 16 + r * 2);
        float sv = vY[i];
        float d  = sv * qy.y;
        float rn = rintf(d);
        float e  = fmaf(-rn, qy.x, sv) * qy.y;
        vY[i]    = fmaf(e*e, e, rn) * qy.x;
    }
    idct8(vY);
    __syncwarp();            // stage-1 reads done in all lanes before overwrite
    writeY(vY, ybg, r);

    fdct8p(pUV);
    #pragma unroll
    for (int i = 0; i < 8; ++i) {
        float2 qc = *(const float2*)(qt + 128 + i * 16 + r * 2);
        float2 s = unpk(pUV[i]);
        float d0 = s.x * qc.y, d1 = s.y * qc.y;
        float r0 = rintf(d0), r1 = rintf(d1);
        float e0 = fmaf(-r0, qc.x, s.x) * qc.y;
        float e1 = fmaf(-r1, qc.x, s.y) * qc.y;
        pUV[i] = pk(fmaf(e0*e0, e0, r0) * qc.x,
                    fmaf(e1*e1, e1, r1) * qc.x);
    }
    idct8p(pUV);
    writeUV(pUV, uvbg, r);
    __syncwarp();
    readY(vY, ybg, r);
    readUV(pUV, uvbg, r);

    // ---- stage 4: row IDCT ----
    idct8(vY);
    idct8p(pUV);

    // ---- folded inverse color + normalize + store ----
    #pragma unroll
    for (int h = 0; h < 2; ++h) {
        float4 Ro, Go, Bo;
        #pragma unroll
        for (int k = 0; k < 4; ++k) {
            int c = h*4 + k;
            float yv = vY[c];
            float2 uvv = unpk(pUV[c]);
            float u = uvv.x, v = uvv.y;
            ((float*)&Ro)[k] = fmaf(yv, NC_A0, fmaf(u, NC_B0, fmaf(v, NC_C0, NC_K0)));
            ((float*)&Go)[k] = fmaf(yv, NC_A1, fmaf(u, NC_B1, fmaf(v, NC_C1, NC_K1)));
            ((float*)&Bo)[k] = fmaf(yv, NC_A2, fmaf(u, NC_B2, fmaf(v, NC_C2, NC_K2)));
        }
        *(float4*)(out + base + h*4)           = Ro;
        *(float4*)(out + base + PLANE + h*4)   = Go;
        *(float4*)(out + base + 2*PLANE + h*4) = Bo;
    }
}

extern "C" void kernel_launch(void* const* d_in, const int* in_sizes, int n_in,
                              void* d_out, int out_size)
{
    const float* in = (const float*)d_in[0];
    float* out = (float*)d_out;
    dim3 grid(IMG_W / 256, IMG_H / 8);
    jpeg_roundtrip_kernel<<<grid, 256>>>(in, out);
}

// round 10
// speedup vs baseline: 1.0014x; 1.0014x over previous
#include <cuda_runtime.h>
#include <cstring>

// Fused JPEG round-trip. Thread owns row r of TWO vertically adjacent 8x8
// blocks (software-pipelined: all 12 RGB loads issued up front). Y scalar,
// U+V packed f32x2. Transposes via per-warp conflict-free smem.
// 128-thread CTAs, launch_bounds(128,7): 2048 CTAs -> 1.98 waves.
// Input : d_in[0] = float32 [1,3,2048,2048]; Output: float32 [1,3*2048*2048]

#define IMG_W  2048
#define IMG_H  2048
#define PLANE  (IMG_W * IMG_H)

#define C1 0.4903926402f
#define C2 0.4619397663f
#define C3 0.4157348062f
#define C4 0.3535533906f
#define C5 0.2777851165f
#define C6 0.1913417162f
#define C7 0.0975451610f

__constant__ float cQf[128] = {
    16,11,10,16,24,40,51,61,  12,12,14,19,26,58,60,55,
    14,13,16,24,40,57,69,56,  14,17,22,29,51,87,80,62,
    18,22,37,56,68,109,103,77, 24,35,55,64,81,104,113,92,
    49,64,78,87,103,121,120,101, 72,92,95,98,112,100,103,99,
    17,18,24,47,99,99,99,99,  18,21,26,66,99,99,99,99,
    24,26,56,99,99,99,99,99,  47,66,99,99,99,99,99,99,
    99,99,99,99,99,99,99,99,  99,99,99,99,99,99,99,99,
    99,99,99,99,99,99,99,99,  99,99,99,99,99,99,99,99 };
__constant__ float cRQf[128] = {
    1.f/16,1.f/11,1.f/10,1.f/16,1.f/24,1.f/40,1.f/51,1.f/61,
    1.f/12,1.f/12,1.f/14,1.f/19,1.f/26,1.f/58,1.f/60,1.f/55,
    1.f/14,1.f/13,1.f/16,1.f/24,1.f/40,1.f/57,1.f/69,1.f/56,
    1.f/14,1.f/17,1.f/22,1.f/29,1.f/51,1.f/87,1.f/80,1.f/62,
    1.f/18,1.f/22,1.f/37,1.f/56,1.f/68,1.f/109,1.f/103,1.f/77,
    1.f/24,1.f/35,1.f/55,1.f/64,1.f/81,1.f/104,1.f/113,1.f/92,
    1.f/49,1.f/64,1.f/78,1.f/87,1.f/103,1.f/121,1.f/120,1.f/101,
    1.f/72,1.f/92,1.f/95,1.f/98,1.f/112,1.f/100,1.f/103,1.f/99,
    1.f/17,1.f/18,1.f/24,1.f/47,1.f/99,1.f/99,1.f/99,1.f/99,
    1.f/18,1.f/21,1.f/26,1.f/66,1.f/99,1.f/99,1.f/99,1.f/99,
    1.f/24,1.f/26,1.f/56,1.f/99,1.f/99,1.f/99,1.f/99,1.f/99,
    1.f/47,1.f/66,1.f/99,1.f/99,1.f/99,1.f/99,1.f/99,1.f/99,
    1.f/99,1.f/99,1.f/99,1.f/99,1.f/99,1.f/99,1.f/99,1.f/99,
    1.f/99,1.f/99,1.f/99,1.f/99,1.f/99,1.f/99,1.f/99,1.f/99,
    1.f/99,1.f/99,1.f/99,1.f/99,1.f/99,1.f/99,1.f/99,1.f/99,
    1.f/99,1.f/99,1.f/99,1.f/99,1.f/99,1.f/99,1.f/99,1.f/99 };

// Folded inverse-color + normalization (validated R5-R9)
#define NC_A0 0.0158730159f
#define NC_B0 (-1.93476190e-8f)
#define NC_C0 0.0222539619f
#define NC_K0 (-4.8373935f)
#define NC_A1 0.0161030596f
#define NC_B1 (-0.0055416377f)
#define NC_C1 (-0.0114997768f)
#define NC_K1 0.2006247f
#define NC_A2 0.0149925037f
#define NC_B2 0.0265667181f
#define NC_C2 6.09145427e-9f
#define NC_K2 (-5.1081869f)

typedef unsigned long long ull;

__device__ __forceinline__ ull pk(float lo, float hi) {
    float2 t = make_float2(lo, hi); ull r; memcpy(&r, &t, 8); return r;
}
__device__ __forceinline__ ull pk1(float x) { return pk(x, x); }
__device__ __forceinline__ float2 unpk(ull a) {
    float2 t; memcpy(&t, &a, 8); return t;
}
__device__ __forceinline__ ull padd(ull a, ull b) {
    ull r; asm("add.rn.f32x2 %0,%1,%2;" : "=l"(r) : "l"(a), "l"(b)); return r;
}
__device__ __forceinline__ ull pmul(ull a, ull b) {
    ull r; asm("mul.rn.f32x2 %0,%1,%2;" : "=l"(r) : "l"(a), "l"(b)); return r;
}
__device__ __forceinline__ ull pfma(ull a, ull b, ull c) {
    ull r; asm("fma.rn.f32x2 %0,%1,%2,%3;" : "=l"(r) : "l"(a), "l"(b), "l"(c)); return r;
}
__device__ __forceinline__ ull psub(ull a, ull b) { return pfma(b, pk1(-1.0f), a); }

__device__ __forceinline__ void fdct8(float v[8]) {
    float e0=v[0]+v[7], e1=v[1]+v[6], e2=v[2]+v[5], e3=v[3]+v[4];
    float o0=v[0]-v[7], o1=v[1]-v[6], o2=v[2]-v[5], o3=v[3]-v[4];
    float s03=e0+e3, s12=e1+e2, d03=e0-e3, d12=e1-e2;
    v[0]=C4*(s03+s12);
    v[4]=C4*(s03-s12);
    v[2]=fmaf(C2,d03, C6*d12);
    v[6]=fmaf(C6,d03,-C2*d12);
    v[1]=fmaf(C1,o0,fmaf( C3,o1,fmaf( C5,o2, C7*o3)));
    v[3]=fmaf(C3,o0,fmaf(-C7,o1,fmaf(-C1,o2,-C5*o3)));
    v[5]=fmaf(C5,o0,fmaf(-C1,o1,fmaf( C7,o2, C3*o3)));
    v[7]=fmaf(C7,o0,fmaf(-C5,o1,fmaf( C3,o2,-C1*o3)));
}
__device__ __forceinline__ void idct8(float v[8]) {
    float sp=C4*(v[0]+v[4]), sm=C4*(v[0]-v[4]);
    float t1=fmaf(C2,v[2], C6*v[6]);
    float t2=fmaf(C6,v[2],-C2*v[6]);
    float E0=sp+t1, E1=sm+t2, E2=sm-t2, E3=sp-t1;
    float O0=fmaf(C1,v[1],fmaf( C3,v[3],fmaf( C5,v[5], C7*v[7])));
    float O1=fmaf(C3,v[1],fmaf(-C7,v[3],fmaf(-C1,v[5],-C5*v[7])));
    float O2=fmaf(C5,v[1],fmaf(-C1,v[3],fmaf( C7,v[5], C3*v[7])));
    float O3=fmaf(C7,v[1],fmaf(-C5,v[3],fmaf( C3,v[5],-C1*v[7])));
    v[0]=E0+O0; v[7]=E0-O0;
    v[1]=E1+O1; v[6]=E1-O1;
    v[2]=E2+O2; v[5]=E2-O2;
    v[3]=E3+O3; v[4]=E3-O3;
}
__device__ __forceinline__ void fdct8p(ull v[8]) {
    ull e0=padd(v[0],v[7]), e1=padd(v[1],v[6]), e2=padd(v[2],v[5]), e3=padd(v[3],v[4]);
    ull o0=psub(v[0],v[7]), o1=psub(v[1],v[6]), o2=psub(v[2],v[5]), o3=psub(v[3],v[4]);
    ull s03=padd(e0,e3), s12=padd(e1,e2), d03=psub(e0,e3), d12=psub(e1,e2);
    v[0]=pmul(pk1(C4), padd(s03,s12));
    v[4]=pmul(pk1(C4), psub(s03,s12));
    v[2]=pfma(pk1(C2),d03, pmul(pk1( C6),d12));
    v[6]=pfma(pk1(C6),d03, pmul(pk1(-C2),d12));
    v[1]=pfma(pk1(C1),o0, pfma(pk1( C3),o1, pfma(pk1( C5),o2, pmul(pk1( C7),o3))));
    v[3]=pfma(pk1(C3),o0, pfma(pk1(-C7),o1, pfma(pk1(-C1),o2, pmul(pk1(-C5),o3))));
    v[5]=pfma(pk1(C5),o0, pfma(pk1(-C1),o1, pfma(pk1( C7),o2, pmul(pk1( C3),o3))));
    v[7]=pfma(pk1(C7),o0, pfma(pk1(-C5),o1, pfma(pk1( C3),o2, pmul(pk1(-C1),o3))));
}
__device__ __forceinline__ void idct8p(ull v[8]) {
    ull sp=pmul(pk1(C4), padd(v[0],v[4]));
    ull sm=pmul(pk1(C4), psub(v[0],v[4]));
    ull t1=pfma(pk1(C2),v[2], pmul(pk1( C6),v[6]));
    ull t2=pfma(pk1(C6),v[2], pmul(pk1(-C2),v[6]));
    ull E0=padd(sp,t1), E1=padd(sm,t2), E2=psub(sm,t2), E3=psub(sp,t1);
    ull O0=pfma(pk1(C1),v[1], pfma(pk1( C3),v[3], pfma(pk1( C5),v[5], pmul(pk1( C7),v[7]))));
    ull O1=pfma(pk1(C3),v[1], pfma(pk1(-C7),v[3], pfma(pk1(-C1),v[5], pmul(pk1(-C5),v[7]))));
    ull O2=pfma(pk1(C5),v[1], pfma(pk1(-C1),v[3], pfma(pk1( C7),v[5], pmul(pk1( C3),v[7]))));
    ull O3=pfma(pk1(C7),v[1], pfma(pk1(-C5),v[3], pfma(pk1( C3),v[5], pmul(pk1(-C1),v[7]))));
    v[0]=padd(E0,O0); v[7]=psub(E0,O0);
    v[1]=padd(E1,O1); v[6]=psub(E1,O1);
    v[2]=padd(E2,O2); v[5]=psub(E2,O2);
    v[3]=padd(E3,O3); v[4]=psub(E3,O3);
}

#define RPY 12
#define GPY 104
#define RPU 10
#define GPU 84

__device__ __forceinline__ void writeY(const float vy[8], float* ybg, int r) {
    float* yw = ybg + RPY * r;
    *(float4*)(yw)     = make_float4(vy[0], vy[1], vy[2], vy[3]);
    *(float4*)(yw + 4) = make_float4(vy[4], vy[5], vy[6], vy[7]);
}
__device__ __forceinline__ void writeUV(const ull uv[8], ull* uvbg, int r) {
    ull* uw = uvbg + RPU * r;
    #pragma unroll
    for (int k = 0; k < 8; k += 2)
        *(ulonglong2*)(uw + k) = make_ulonglong2(uv[k], uv[k+1]);
}
__device__ __forceinline__ void readY(float vy[8], const float* ybg, int r) {
    #pragma unroll
    for (int k = 0; k < 8; ++k) vy[k] = ybg[RPY * k + r];
}
__device__ __forceinline__ void readUV(ull uv[8], const ull* uvbg, int r) {
    #pragma unroll
    for (int k = 0; k < 8; ++k) uv[k] = uvbg[RPU * k + r];
}

// process one 8x8 tile (RGB in registers) -> writes outputs
__device__ __forceinline__ void process_tile(
    const float4 Ra, const float4 Rb, const float4 Ga, const float4 Gb,
    const float4 Ba, const float4 Bb,
    float* ybg, ull* uvbg, const float* qt, int r, float* out, int base)
{
    float R[8] = {Ra.x,Ra.y,Ra.z,Ra.w, Rb.x,Rb.y,Rb.z,Rb.w};
    float G[8] = {Ga.x,Ga.y,Ga.z,Ga.w, Gb.x,Gb.y,Gb.z,Gb.w};
    float B[8] = {Ba.x,Ba.y,Ba.z,Ba.w, Bb.x,Bb.y,Bb.z,Bb.w};

    float vY[8];
    ull   pUV[8];
    #pragma unroll
    for (int k = 0; k < 8; ++k) {
        vY[k] = 0.299f*R[k] + 0.587f*G[k] + 0.114f*B[k];
        float u = fmaf(-0.168736f, R[k], fmaf(-0.331264f, G[k], fmaf(0.5f, B[k], 128.0f)));
        float v = fmaf(0.5f, R[k], fmaf(-0.418688f, G[k], fmaf(-0.081312f, B[k], 128.0f)));
        pUV[k] = pk(u, v);
    }

    // stage 1: row DCT + transpose
    fdct8(vY);   writeY(vY, ybg, r);
    fdct8p(pUV); writeUV(pUV, uvbg, r);
    __syncwarp();
    readY(vY, ybg, r);
    readUV(pUV, uvbg, r);

    // stage 2: column DCT + quant + column IDCT (Y then UV), transpose back
    fdct8(vY);
    #pragma unroll
    for (int i = 0; i < 8; ++i) {
        float2 qy = *(const float2*)(qt + i * 16 + r * 2);
        float sv = vY[i];
        float d  = sv * qy.y;
        float rn = rintf(d);
        float e  = fmaf(-rn, qy.x, sv) * qy.y;
        vY[i]    = fmaf(e*e, e, rn) * qy.x;
    }
    idct8(vY);
    __syncwarp();          // stage-1 reads complete in all lanes before overwrite
    writeY(vY, ybg, r);

    fdct8p(pUV);
    #pragma unroll
    for (int i = 0; i < 8; ++i) {
        float2 qc = *(const float2*)(qt + 128 + i * 16 + r * 2);
        float2 s = unpk(pUV[i]);
        float d0 = s.x * qc.y, d1 = s.y * qc.y;
        float r0 = rintf(d0), r1 = rintf(d1);
        float e0 = fmaf(-r0, qc.x, s.x) * qc.y;
        float e1 = fmaf(-r1, qc.x, s.y) * qc.y;
        pUV[i] = pk(fmaf(e0*e0, e0, r0) * qc.x,
                    fmaf(e1*e1, e1, r1) * qc.x);
    }
    idct8p(pUV);
    writeUV(pUV, uvbg, r);
    __syncwarp();
    readY(vY, ybg, r);
    readUV(pUV, uvbg, r);
    __syncwarp();          // reads complete before next tile's writes

    // stage 4: row IDCT
    idct8(vY);
    idct8p(pUV);

    // folded inverse color + normalize + store
    #pragma unroll
    for (int h = 0; h < 2; ++h) {
        float4 Ro, Go, Bo;
        #pragma unroll
        for (int k = 0; k < 4; ++k) {
            int c = h*4 + k;
            float yv = vY[c];
            float2 uvv = unpk(pUV[c]);
            float u = uvv.x, v = uvv.y;
            ((float*)&Ro)[k] = fmaf(yv, NC_A0, fmaf(u, NC_B0, fmaf(v, NC_C0, NC_K0)));
            ((float*)&Go)[k] = fmaf(yv, NC_A1, fmaf(u, NC_B1, fmaf(v, NC_C1, NC_K1)));
            ((float*)&Bo)[k] = fmaf(yv, NC_A2, fmaf(u, NC_B2, fmaf(v, NC_C2, NC_K2)));
        }
        *(float4*)(out + base + h*4)           = Ro;
        *(float4*)(out + base + PLANE + h*4)   = Go;
        *(float4*)(out + base + 2*PLANE + h*4) = Bo;
    }
}

__global__ __launch_bounds__(128, 7)
void jpeg_roundtrip_kernel(const float* __restrict__ in, float* __restrict__ out)
{
    __shared__ __align__(16) float yb[4 * 4 * GPY];   // 6656 B
    __shared__ __align__(16) ull  uvb[4 * 4 * GPU];   // 10752 B
    __shared__ float qt[256];

    const int tid  = threadIdx.x;
    const int warp = tid >> 5;
    const int lane = tid & 31;
    const int r    = lane >> 2;
    const int g    = lane & 3;

    {   // build interleaved quant table (2 entries per thread)
        #pragma unroll
        for (int t = tid; t < 256; t += 128) {
            int w  = t & 1, rr = (t >> 1) & 7, ii = (t >> 4) & 7, ch = t >> 7;
            int si = ch * 64 + ii * 8 + rr;
            qt[t] = w ? cRQf[si] : cQf[si];
        }
    }

    float* ybg  = yb  + (warp * 4 + g) * GPY;
    ull*   uvbg = uvb + (warp * 4 + g) * GPU;

    const int x0    = blockIdx.x * 128 + (warp * 4 + g) * 8;
    const int y0    = blockIdx.y * 16 + r;
    const int baseA = y0 * IMG_W + x0;
    const int baseB = baseA + 8 * IMG_W;

    // ---- issue ALL 12 loads up front (tile A + tile B, MLP=12) ----
    const float4 ARa = *(const float4*)(in + baseA);
    const float4 ARb = *(const float4*)(in + baseA + 4);
    const float4 AGa = *(const float4*)(in + baseA + PLANE);
    const float4 AGb = *(const float4*)(in + baseA + PLANE + 4);
    const float4 ABa = *(const float4*)(in + baseA + 2*PLANE);
    const float4 ABb = *(const float4*)(in + baseA + 2*PLANE + 4);
    const float4 BRa = *(const float4*)(in + baseB);
    const float4 BRb = *(const float4*)(in + baseB + 4);
    const float4 BGa = *(const float4*)(in + baseB + PLANE);
    const float4 BGb = *(const float4*)(in + baseB + PLANE + 4);
    const float4 BBa = *(const float4*)(in + baseB + 2*PLANE);
    const float4 BBb = *(const float4*)(in + baseB + 2*PLANE + 4);

    __syncthreads();   // quant table ready

    // tile A computes while tile B's loads are still in flight
    process_tile(ARa, ARb, AGa, AGb, ABa, ABb, ybg, uvbg, qt, r, out, baseA);
    process_tile(BRa, BRb, BGa, BGb, BBa, BBb, ybg, uvbg, qt, r, out, baseB);
}

extern "C" void kernel_launch(void* const* d_in, const int* in_sizes, int n_in,
                              void* d_out, int out_size)
{
    const float* in = (const float*)d_in[0];
    float* out = (float*)d_out;
    dim3 grid(IMG_W / 128, IMG_H / 16);
    jpeg_roundtrip_kernel<<<grid, 128>>>(in, out);
}